// round 1
// baseline (speedup 1.0000x reference)
#include <cuda_runtime.h>
#include <math.h>

#define NN 20000
#define EE 100000
#define RR 1000
#define FF 128
#define HH 4
#define LL 4
#define HC 512          // HH*FF
#define ET (EE + NN)    // edges + self loops

// ---------------- scratch (static device globals; no allocation) -------------
__device__ __align__(256) float    g_h0[NN * FF];
__device__ __align__(256) float    g_h1[NN * FF];
__device__ __align__(256) float    g_xl[(size_t)NN * HC];
__device__ __align__(256) float    g_xr[(size_t)NN * HC];
__device__ __align__(256) float    g_relemb[(size_t)LL * RR * HC];
__device__ __align__(256) float    g_eemean[LL * HC];
__device__ __align__(256) float    g_eamean[FF];
__device__ __align__(256) int      g_hist[RR];
__device__ __align__(256) float    g_p[(size_t)ET * HH];   // logits, then p=exp(...)
__device__ __align__(256) unsigned g_m[NN * HH];           // ordered-encoded float max
__device__ __align__(256) float    g_denom[NN * HH];

// ---------------- helpers ----------------------------------------------------
__device__ __forceinline__ float lrelu(float v) { return v > 0.f ? v : 0.2f * v; }

__device__ __forceinline__ unsigned fenc(float f) {
    unsigned u = __float_as_uint(f);
    return (u & 0x80000000u) ? ~u : (u | 0x80000000u);
}
__device__ __forceinline__ float fdec(unsigned u) {
    u = (u & 0x80000000u) ? (u & 0x7FFFFFFFu) : ~u;
    return __uint_as_float(u);
}

__device__ __forceinline__ const float* sel_in(const float* p, int s) {
    return s == 0 ? p : (s == 1 ? g_h0 : g_h1);
}
__device__ __forceinline__ float* sel_out(int s) {
    return s == 1 ? g_h0 : g_h1;
}

// ---------------- precompute kernels -----------------------------------------
__global__ void k_zero_hist() {
    int i = blockIdx.x * blockDim.x + threadIdx.x;
    if (i < RR) g_hist[i] = 0;
}

__global__ void k_hist(const int* __restrict__ relidx) {
    int e = blockIdx.x * blockDim.x + threadIdx.x;
    if (e < EE) atomicAdd(&g_hist[relidx[e]], 1);
}

// ea_mean[f] = sum_r hist[r] * relations[r][f] / E
__global__ void k_eamean(const float* __restrict__ relations) {
    int f = threadIdx.x;  // 128 threads, 1 block
    float s = 0.f;
    for (int r = 0; r < RR; r++)
        s += (float)g_hist[r] * relations[r * FF + f];
    g_eamean[f] = s * (1.0f / EE);
}

// ee_mean[l][c] = sum_f ea_mean[f] * We[l][f][c]
__global__ void k_eemean(const float* __restrict__ We) {
    int idx = blockIdx.x * blockDim.x + threadIdx.x;
    if (idx >= LL * HC) return;
    int l = idx / HC, c = idx % HC;
    const float* W = We + (size_t)l * FF * HC;
    float s = 0.f;
    #pragma unroll 8
    for (int f = 0; f < FF; f++)
        s += g_eamean[f] * W[f * HC + c];
    g_eemean[idx] = s;
}

// ---------------- SGEMM: C[M,512] = A[M,128] @ B[128,512] (+bias) ------------
// csel: 0 -> g_xl, 1 -> g_xr, 2 -> g_relemb (z-batched over layers)
#define BM 128
#define BN 128
#define BK 8
#define TM 8
#define TN 8
__global__ void __launch_bounds__(256)
k_gemm(const float* __restrict__ Ap, int asel,
       const float* __restrict__ B, long bStrideZ,
       const float* __restrict__ bias, int hasb,
       int csel, int M) {
    const float* A = sel_in(Ap, asel);
    int bz = blockIdx.z;
    B += (size_t)bz * bStrideZ;
    float* C;
    if (csel == 0) C = g_xl;
    else if (csel == 1) C = g_xr;
    else C = g_relemb + (size_t)bz * RR * HC;

    int bm = blockIdx.y * BM, bn = blockIdx.x * BN;
    __shared__ float As[BK][BM];
    __shared__ float Bs[BK][BN];
    int tid = threadIdx.x;
    int aRow = tid >> 1, aCol = (tid & 1) * 4;     // A tile load: 128 rows x 8 k
    int bRow = tid >> 5, bCol = (tid & 31) * 4;    // B tile load: 8 k x 128 cols
    int tx = tid & 15, ty = tid >> 4;

    float acc[TM][TN];
    #pragma unroll
    for (int i = 0; i < TM; i++)
        #pragma unroll
        for (int j = 0; j < TN; j++) acc[i][j] = 0.f;

    for (int k0 = 0; k0 < FF; k0 += BK) {
        float4 va = make_float4(0.f, 0.f, 0.f, 0.f);
        int gr = bm + aRow;
        if (gr < M) va = *(const float4*)(A + (size_t)gr * FF + k0 + aCol);
        As[aCol + 0][aRow] = va.x;
        As[aCol + 1][aRow] = va.y;
        As[aCol + 2][aRow] = va.z;
        As[aCol + 3][aRow] = va.w;
        float4 vb = *(const float4*)(B + (size_t)(k0 + bRow) * HC + bn + bCol);
        *(float4*)&Bs[bRow][bCol] = vb;
        __syncthreads();
        #pragma unroll
        for (int k = 0; k < BK; k++) {
            float ra[TM], rb[TN];
            #pragma unroll
            for (int i = 0; i < TM; i++) ra[i] = As[k][ty * TM + i];
            #pragma unroll
            for (int j = 0; j < TN; j++) rb[j] = Bs[k][tx * TN + j];
            #pragma unroll
            for (int i = 0; i < TM; i++)
                #pragma unroll
                for (int j = 0; j < TN; j++) acc[i][j] += ra[i] * rb[j];
        }
        __syncthreads();
    }

    #pragma unroll
    for (int i = 0; i < TM; i++) {
        int gr = bm + ty * TM + i;
        if (gr >= M) continue;
        float* cp = C + (size_t)gr * HC + bn + tx * TN;
        #pragma unroll
        for (int j = 0; j < TN; j += 4) {
            float4 v;
            int gc = bn + tx * TN + j;
            float b0 = hasb ? bias[gc + 0] : 0.f;
            float b1 = hasb ? bias[gc + 1] : 0.f;
            float b2 = hasb ? bias[gc + 2] : 0.f;
            float b3 = hasb ? bias[gc + 3] : 0.f;
            v.x = acc[i][j + 0] + b0;
            v.y = acc[i][j + 1] + b1;
            v.z = acc[i][j + 2] + b2;
            v.w = acc[i][j + 3] + b3;
            *(float4*)(cp + j) = v;
        }
    }
}

// ---------------- per-layer kernels ------------------------------------------
// init hout = bias (so atomics accumulate on top), m = enc(-inf-ish)=0, denom=0
__global__ void k_init(const float* __restrict__ bias_l, int osel) {
    int idx = blockIdx.x * blockDim.x + threadIdx.x;
    if (idx < NN * HH) { g_m[idx] = 0u; g_denom[idx] = 0.f; }
    if (idx < NN * FF) sel_out(osel)[idx] = bias_l[idx % FF];
}

// warp per edge: logits[e][h] = sum_c att[h][c]*lrelu(xl[src]+xr[dst]+ee)
__global__ void __launch_bounds__(256)
k_logits(const int* __restrict__ eidx, const int* __restrict__ ridx,
         const float* __restrict__ att_l, int layer) {
    int warp = blockIdx.x * 8 + (threadIdx.x >> 5);
    int lane = threadIdx.x & 31;
    if (warp >= ET) return;
    int e = warp, src, dst;
    const float* ee;
    if (e < EE) {
        src = eidx[e];
        dst = eidx[EE + e];
        ee = g_relemb + (size_t)layer * RR * HC + (size_t)ridx[e] * HC;
    } else {
        src = dst = e - EE;
        ee = g_eemean + layer * HC;
    }
    const float* pxl = g_xl + (size_t)src * HC;
    const float* pxr = g_xr + (size_t)dst * HC;
    int c = lane * 4;
    #pragma unroll
    for (int h = 0; h < HH; h++) {
        int o = h * FF + c;
        float4 a = *(const float4*)(pxl + o);
        float4 b = *(const float4*)(pxr + o);
        float4 g = *(const float4*)(ee + o);
        float4 w = *(const float4*)(att_l + o);
        float s = w.x * lrelu(a.x + b.x + g.x) + w.y * lrelu(a.y + b.y + g.y)
                + w.z * lrelu(a.z + b.z + g.z) + w.w * lrelu(a.w + b.w + g.w);
        #pragma unroll
        for (int off = 16; off > 0; off >>= 1) s += __shfl_xor_sync(0xFFFFFFFFu, s, off);
        if (lane == 0) {
            g_p[(size_t)e * HH + h] = s;
            atomicMax(&g_m[dst * HH + h], fenc(s));
        }
    }
}

// p = exp(logit - m[dst]); denom[dst] += p
__global__ void k_exp(const int* __restrict__ eidx) {
    int idx = blockIdx.x * blockDim.x + threadIdx.x;
    if (idx >= ET * HH) return;
    int e = idx >> 2, h = idx & 3;
    int dst = (e < EE) ? eidx[EE + e] : (e - EE);
    float p = __expf(g_p[idx] - fdec(g_m[dst * HH + h]));
    g_p[idx] = p;
    atomicAdd(&g_denom[dst * HH + h], p);
}

// warp per edge: hout[dst][f] += (1/H) * sum_h alpha[e][h] * xl[src][h][f]
__global__ void __launch_bounds__(256)
k_scatter(const int* __restrict__ eidx, int osel) {
    int warp = blockIdx.x * 8 + (threadIdx.x >> 5);
    int lane = threadIdx.x & 31;
    if (warp >= ET) return;
    int e = warp, src, dst;
    if (e < EE) { src = eidx[e]; dst = eidx[EE + e]; }
    else        { src = dst = e - EE; }
    float al[HH];
    #pragma unroll
    for (int h = 0; h < HH; h++)
        al[h] = g_p[(size_t)e * HH + h] / g_denom[dst * HH + h] * 0.25f;
    const float* px = g_xl + (size_t)src * HC;
    int c = lane * 4;
    float4 acc = make_float4(0.f, 0.f, 0.f, 0.f);
    #pragma unroll
    for (int h = 0; h < HH; h++) {
        float4 v = *(const float4*)(px + h * FF + c);
        acc.x += al[h] * v.x;
        acc.y += al[h] * v.y;
        acc.z += al[h] * v.z;
        acc.w += al[h] * v.w;
    }
    float* o = sel_out(osel) + (size_t)dst * FF + c;
    atomicAdd(o + 0, acc.x);
    atomicAdd(o + 1, acc.y);
    atomicAdd(o + 2, acc.z);
    atomicAdd(o + 3, acc.w);
}

// ---------------- output -----------------------------------------------------
__global__ void k_final(const float* __restrict__ relations, float* __restrict__ out,
                        int out_size) {
    int idx = blockIdx.x * blockDim.x + threadIdx.x;
    if (idx >= out_size) return;
    if (idx < NN * FF) out[idx] = g_h1[idx];
    else {
        int r = idx - NN * FF;
        if (r < RR * FF) out[idx] = relations[r];
        else out[idx] = 0.f;
    }
}

// ---------------- launch -----------------------------------------------------
extern "C" void kernel_launch(void* const* d_in, const int* in_sizes, int n_in,
                              void* d_out, int out_size) {
    const float* x         = (const float*)d_in[0];
    const int*   eidx      = (const int*)  d_in[1];
    const float* relations = (const float*)d_in[2];
    const int*   ridx      = (const int*)  d_in[3];
    const float* Wl        = (const float*)d_in[4];
    const float* bl        = (const float*)d_in[5];
    const float* Wr        = (const float*)d_in[6];
    const float* br        = (const float*)d_in[7];
    const float* We        = (const float*)d_in[8];
    const float* att       = (const float*)d_in[9];
    const float* bias      = (const float*)d_in[10];
    float* out = (float*)d_out;

    // ---- precompute: relation histogram, mean edge-attr, relation embeddings
    k_zero_hist<<<1, 1024>>>();
    k_hist<<<(EE + 255) / 256, 256>>>(ridx);
    k_eamean<<<1, FF>>>(relations);
    {
        dim3 grid(HC / BN, (RR + BM - 1) / BM, LL);
        k_gemm<<<grid, 256>>>(relations, 0, We, (long)FF * HC, nullptr, 0, 2, RR);
    }
    k_eemean<<<(LL * HC + 255) / 256, 256>>>(We);

    // ---- layers ----
    const int asel[LL] = {0, 1, 2, 1};
    const int osel[LL] = {1, 2, 1, 2};
    dim3 ggrid(HC / BN, (NN + BM - 1) / BM, 1);
    int eb = (ET + 7) / 8;                 // blocks for warp-per-edge kernels

    for (int l = 0; l < LL; l++) {
        k_gemm<<<ggrid, 256>>>(x, asel[l], Wl + (size_t)l * FF * HC, 0,
                               bl + (size_t)l * HC, 1, 0, NN);
        k_gemm<<<ggrid, 256>>>(x, asel[l], Wr + (size_t)l * FF * HC, 0,
                               br + (size_t)l * HC, 1, 1, NN);
        k_init<<<(NN * FF + 255) / 256, 256>>>(bias + (size_t)l * FF, osel[l]);
        k_logits<<<eb, 256>>>(eidx, ridx, att + (size_t)l * HH * FF, l);
        k_exp<<<(ET * HH + 255) / 256, 256>>>(eidx);
        k_scatter<<<eb, 256>>>(eidx, osel[l]);
    }

    k_final<<<(out_size + 255) / 256, 256>>>(relations, out, out_size);
}

// round 2
// speedup vs baseline: 1.5115x; 1.5115x over previous
#include <cuda_runtime.h>
#include <math.h>

#define NN 20000
#define EE 100000
#define RR 1000
#define FF 128
#define HH 4
#define LL 4
#define HC 512          // HH*FF
#define ET (EE + NN)    // edges + self loops

// ---------------- scratch (static device globals; no allocation) -------------
__device__ __align__(256) float    g_h0[NN * FF];
__device__ __align__(256) float    g_h1[NN * FF];
__device__ __align__(256) float    g_xl[(size_t)NN * HC];
__device__ __align__(256) float    g_xr[(size_t)NN * HC];
__device__ __align__(256) float    g_relemb[(size_t)LL * RR * HC];
__device__ __align__(256) float    g_eemean[LL * HC];
__device__ __align__(256) float    g_eamean[FF];
__device__ __align__(256) int      g_hist[RR];
__device__ __align__(256) float    g_p[(size_t)ET * HH];   // logits, then p=exp(...)
__device__ __align__(256) unsigned g_m[NN * HH];           // ordered-encoded float max
__device__ __align__(256) float    g_denom[NN * HH];

// ---------------- helpers ----------------------------------------------------
__device__ __forceinline__ float lrelu(float v) { return v > 0.f ? v : 0.2f * v; }

__device__ __forceinline__ unsigned fenc(float f) {
    unsigned u = __float_as_uint(f);
    return (u & 0x80000000u) ? ~u : (u | 0x80000000u);
}
__device__ __forceinline__ float fdec(unsigned u) {
    u = (u & 0x80000000u) ? (u & 0x7FFFFFFFu) : ~u;
    return __uint_as_float(u);
}

__device__ __forceinline__ const float* sel_in(const float* p, int s) {
    return s == 0 ? p : (s == 1 ? g_h0 : g_h1);
}
__device__ __forceinline__ float* sel_out(int s) {
    return s == 1 ? g_h0 : g_h1;
}

__device__ __forceinline__ unsigned to_tf32(float v) {
    unsigned r;
    asm("cvt.rna.tf32.f32 %0, %1;" : "=r"(r) : "f"(v));
    return r;
}

// ---------------- precompute kernels -----------------------------------------
__global__ void k_zero_hist() {
    int i = blockIdx.x * blockDim.x + threadIdx.x;
    if (i < RR) g_hist[i] = 0;
}

__global__ void k_hist(const int* __restrict__ relidx) {
    int e = blockIdx.x * blockDim.x + threadIdx.x;
    if (e < EE) atomicAdd(&g_hist[relidx[e]], 1);
}

// ea_mean[f] = sum_r hist[r] * relations[r][f] / E
__global__ void k_eamean(const float* __restrict__ relations) {
    int f = threadIdx.x;  // 128 threads, 1 block
    float s = 0.f;
    for (int r = 0; r < RR; r++)
        s += (float)g_hist[r] * relations[r * FF + f];
    g_eamean[f] = s * (1.0f / EE);
}

// ee_mean[l][c] = sum_f ea_mean[f] * We[l][f][c]
__global__ void k_eemean(const float* __restrict__ We) {
    int idx = blockIdx.x * blockDim.x + threadIdx.x;
    if (idx >= LL * HC) return;
    int l = idx / HC, c = idx % HC;
    const float* W = We + (size_t)l * FF * HC;
    float s = 0.f;
    #pragma unroll 8
    for (int f = 0; f < FF; f++)
        s += g_eamean[f] * W[f * HC + c];
    g_eemean[idx] = s;
}

// ---------------- tf32 tensor-core GEMM --------------------------------------
// C[M,512] = A[M,128] @ B[128,512] (+bias)
// CTA tile 128x128, BK=32 (4 chunks), 8 warps (2x4), warp tile 64x32.
// mode 0: z in {0,1}: B = z? B1:B0, bias = z? bias1:bias0, C = z? g_xr:g_xl
// mode 1: z = layer:  B = B0 + z*FF*HC, C = g_relemb + z*RR*HC, no bias
#define TBM 128
#define TBN 128
#define TBK 32

__device__ __forceinline__ void mma_tf32(float c[4], const unsigned a[4],
                                         const unsigned b[2]) {
    asm volatile(
        "mma.sync.aligned.m16n8k8.row.col.f32.tf32.tf32.f32 "
        "{%0,%1,%2,%3}, {%4,%5,%6,%7}, {%8,%9}, {%0,%1,%2,%3};"
        : "+f"(c[0]), "+f"(c[1]), "+f"(c[2]), "+f"(c[3])
        : "r"(a[0]), "r"(a[1]), "r"(a[2]), "r"(a[3]), "r"(b[0]), "r"(b[1]));
}

__global__ void __launch_bounds__(256, 2)
k_tgemm(const float* __restrict__ Ap, int asel,
        const float* __restrict__ B0, const float* __restrict__ B1,
        const float* __restrict__ bias0, const float* __restrict__ bias1,
        int mode, int M)
{
    // fragment-permuted staging buffers (conflict-free fragment loads)
    __shared__ __align__(16) unsigned Aperm[4 * 8 * 32 * 4];   // [ks][mt][lane][slot]
    __shared__ __align__(16) unsigned Bperm[4 * 16 * 32 * 2];  // [ks][nt][lane][slot]

    const float* A = sel_in(Ap, asel);
    const float* B;
    const float* bias = nullptr;
    float* C;
    int z = blockIdx.z;
    if (mode == 0) {
        B    = z ? B1 : B0;
        bias = z ? bias1 : bias0;
        C    = z ? g_xr : g_xl;
    } else {
        B = B0 + (size_t)z * FF * HC;
        C = g_relemb + (size_t)z * RR * HC;
    }

    int bm = blockIdx.y * TBM, bn = blockIdx.x * TBN;
    int tid = threadIdx.x, lane = tid & 31, wid = tid >> 5;
    int warp_m = wid & 1, warp_n = wid >> 1;   // 2 x 4 warp grid

    float c[4][4][4];
    #pragma unroll
    for (int i = 0; i < 4; i++)
        #pragma unroll
        for (int j = 0; j < 4; j++)
            #pragma unroll
            for (int k = 0; k < 4; k++) c[i][j][k] = 0.f;

    for (int k0 = 0; k0 < FF; k0 += TBK) {
        // ---- stage A chunk (128 rows x 32 k) into fragment-permuted layout
        #pragma unroll
        for (int i = 0; i < 16; i++) {
            int idx = i * 256 + tid;
            int row = idx >> 5, kk = idx & 31;
            float v = 0.f;
            int gr = bm + row;
            if (gr < M) v = A[(size_t)gr * FF + k0 + kk];
            unsigned tv = to_tf32(v);
            int ks = kk >> 3, q = kk & 7, mt = row >> 4, r16 = row & 15;
            int ln   = ((r16 & 7) << 2) | (q & 3);
            int slot = (r16 >> 3) + ((q >> 2) << 1);
            Aperm[(((ks << 3) | mt) << 7) + (ln << 2) + slot] = tv;
        }
        // ---- stage B chunk (32 k x 128 cols)
        #pragma unroll
        for (int i = 0; i < 16; i++) {
            int idx = i * 256 + tid;
            int kk = idx >> 7, col = idx & 127;
            float v = B[(size_t)(k0 + kk) * HC + bn + col];
            unsigned tv = to_tf32(v);
            int ks = kk >> 3, q = kk & 7, nt = col >> 3;
            int ln   = ((col & 7) << 2) | (q & 3);
            int slot = q >> 2;
            Bperm[(((ks << 4) | nt) << 6) + (ln << 1) + slot] = tv;
        }
        __syncthreads();

        #pragma unroll
        for (int ks = 0; ks < 4; ks++) {
            unsigned a[4][4], b[4][2];
            #pragma unroll
            for (int mt = 0; mt < 4; mt++) {
                int mt_g = warp_m * 4 + mt;
                uint4 v = *(const uint4*)&Aperm[(((ks << 3) | mt_g) << 7) + (lane << 2)];
                a[mt][0] = v.x; a[mt][1] = v.y; a[mt][2] = v.z; a[mt][3] = v.w;
            }
            #pragma unroll
            for (int nt = 0; nt < 4; nt++) {
                int nt_g = warp_n * 4 + nt;
                uint2 v = *(const uint2*)&Bperm[(((ks << 4) | nt_g) << 6) + (lane << 1)];
                b[nt][0] = v.x; b[nt][1] = v.y;
            }
            #pragma unroll
            for (int mt = 0; mt < 4; mt++)
                #pragma unroll
                for (int nt = 0; nt < 4; nt++)
                    mma_tf32(c[mt][nt], a[mt], b[nt]);
        }
        __syncthreads();
    }

    // ---- epilogue: bias + store (float2 per fragment half)
    #pragma unroll
    for (int mt = 0; mt < 4; mt++) {
        int row = bm + warp_m * 64 + mt * 16 + (lane >> 2);
        #pragma unroll
        for (int nt = 0; nt < 4; nt++) {
            int col = bn + warp_n * 32 + nt * 8 + ((lane & 3) << 1);
            float b0 = 0.f, b1 = 0.f;
            if (bias) { b0 = bias[col]; b1 = bias[col + 1]; }
            if (row < M) {
                float2 v = make_float2(c[mt][nt][0] + b0, c[mt][nt][1] + b1);
                *(float2*)&C[(size_t)row * HC + col] = v;
            }
            if (row + 8 < M) {
                float2 v = make_float2(c[mt][nt][2] + b0, c[mt][nt][3] + b1);
                *(float2*)&C[(size_t)(row + 8) * HC + col] = v;
            }
        }
    }
}

// ---------------- per-layer kernels ------------------------------------------
// init hout = bias (so atomics accumulate on top), m = enc(-inf-ish)=0, denom=0
__global__ void k_init(const float* __restrict__ bias_l, int osel) {
    int idx = blockIdx.x * blockDim.x + threadIdx.x;
    if (idx < NN * HH) { g_m[idx] = 0u; g_denom[idx] = 0.f; }
    if (idx < NN * FF) sel_out(osel)[idx] = bias_l[idx % FF];
}

// warp per edge: logits[e][h] = sum_c att[h][c]*lrelu(xl[src]+xr[dst]+ee)
__global__ void __launch_bounds__(256)
k_logits(const int* __restrict__ eidx, const int* __restrict__ ridx,
         const float* __restrict__ att_l, int layer) {
    int warp = blockIdx.x * 8 + (threadIdx.x >> 5);
    int lane = threadIdx.x & 31;
    if (warp >= ET) return;
    int e = warp, src, dst;
    const float* ee;
    if (e < EE) {
        src = eidx[e];
        dst = eidx[EE + e];
        ee = g_relemb + (size_t)layer * RR * HC + (size_t)ridx[e] * HC;
    } else {
        src = dst = e - EE;
        ee = g_eemean + layer * HC;
    }
    const float* pxl = g_xl + (size_t)src * HC;
    const float* pxr = g_xr + (size_t)dst * HC;
    int c = lane * 4;
    #pragma unroll
    for (int h = 0; h < HH; h++) {
        int o = h * FF + c;
        float4 a = *(const float4*)(pxl + o);
        float4 b = *(const float4*)(pxr + o);
        float4 g = *(const float4*)(ee + o);
        float4 w = *(const float4*)(att_l + o);
        float s = w.x * lrelu(a.x + b.x + g.x) + w.y * lrelu(a.y + b.y + g.y)
                + w.z * lrelu(a.z + b.z + g.z) + w.w * lrelu(a.w + b.w + g.w);
        #pragma unroll
        for (int off = 16; off > 0; off >>= 1) s += __shfl_xor_sync(0xFFFFFFFFu, s, off);
        if (lane == 0) {
            g_p[(size_t)e * HH + h] = s;
            atomicMax(&g_m[dst * HH + h], fenc(s));
        }
    }
}

// p = exp(logit - m[dst]); denom[dst] += p
__global__ void k_exp(const int* __restrict__ eidx) {
    int idx = blockIdx.x * blockDim.x + threadIdx.x;
    if (idx >= ET * HH) return;
    int e = idx >> 2, h = idx & 3;
    int dst = (e < EE) ? eidx[EE + e] : (e - EE);
    float p = __expf(g_p[idx] - fdec(g_m[dst * HH + h]));
    g_p[idx] = p;
    atomicAdd(&g_denom[dst * HH + h], p);
}

// warp per edge: hout[dst][f] += (1/H) * sum_h alpha[e][h] * xl[src][h][f]
__global__ void __launch_bounds__(256)
k_scatter(const int* __restrict__ eidx, int osel) {
    int warp = blockIdx.x * 8 + (threadIdx.x >> 5);
    int lane = threadIdx.x & 31;
    if (warp >= ET) return;
    int e = warp, src, dst;
    if (e < EE) { src = eidx[e]; dst = eidx[EE + e]; }
    else        { src = dst = e - EE; }
    float al[HH];
    #pragma unroll
    for (int h = 0; h < HH; h++)
        al[h] = g_p[(size_t)e * HH + h] / g_denom[dst * HH + h] * 0.25f;
    const float* px = g_xl + (size_t)src * HC;
    int c = lane * 4;
    float4 acc = make_float4(0.f, 0.f, 0.f, 0.f);
    #pragma unroll
    for (int h = 0; h < HH; h++) {
        float4 v = *(const float4*)(px + h * FF + c);
        acc.x += al[h] * v.x;
        acc.y += al[h] * v.y;
        acc.z += al[h] * v.z;
        acc.w += al[h] * v.w;
    }
    float* o = sel_out(osel) + (size_t)dst * FF + c;
    atomicAdd(o + 0, acc.x);
    atomicAdd(o + 1, acc.y);
    atomicAdd(o + 2, acc.z);
    atomicAdd(o + 3, acc.w);
}

// ---------------- output -----------------------------------------------------
__global__ void k_final(const float* __restrict__ relations, float* __restrict__ out,
                        int out_size) {
    int idx = blockIdx.x * blockDim.x + threadIdx.x;
    if (idx >= out_size) return;
    if (idx < NN * FF) out[idx] = g_h1[idx];
    else {
        int r = idx - NN * FF;
        if (r < RR * FF) out[idx] = relations[r];
        else out[idx] = 0.f;
    }
}

// ---------------- launch -----------------------------------------------------
extern "C" void kernel_launch(void* const* d_in, const int* in_sizes, int n_in,
                              void* d_out, int out_size) {
    const float* x         = (const float*)d_in[0];
    const int*   eidx      = (const int*)  d_in[1];
    const float* relations = (const float*)d_in[2];
    const int*   ridx      = (const int*)  d_in[3];
    const float* Wl        = (const float*)d_in[4];
    const float* bl        = (const float*)d_in[5];
    const float* Wr        = (const float*)d_in[6];
    const float* br        = (const float*)d_in[7];
    const float* We        = (const float*)d_in[8];
    const float* att       = (const float*)d_in[9];
    const float* bias      = (const float*)d_in[10];
    float* out = (float*)d_out;

    // ---- precompute: relation histogram, mean edge-attr, relation embeddings
    k_zero_hist<<<1, 1024>>>();
    k_hist<<<(EE + 255) / 256, 256>>>(ridx);
    k_eamean<<<1, FF>>>(relations);
    {
        dim3 grid(HC / TBN, (RR + TBM - 1) / TBM, LL);
        k_tgemm<<<grid, 256>>>(relations, 0, We, nullptr, nullptr, nullptr, 1, RR);
    }
    k_eemean<<<(LL * HC + 255) / 256, 256>>>(We);

    // ---- layers ----
    const int asel[LL] = {0, 1, 2, 1};
    const int osel[LL] = {1, 2, 1, 2};
    dim3 ggrid(HC / TBN, (NN + TBM - 1) / TBM, 2);   // z: 0 -> xl, 1 -> xr
    int eb = (ET + 7) / 8;                 // blocks for warp-per-edge kernels

    for (int l = 0; l < LL; l++) {
        k_tgemm<<<ggrid, 256>>>(x, asel[l],
                                Wl + (size_t)l * FF * HC, Wr + (size_t)l * FF * HC,
                                bl + (size_t)l * HC, br + (size_t)l * HC,
                                0, NN);
        k_init<<<(NN * FF + 255) / 256, 256>>>(bias + (size_t)l * FF, osel[l]);
        k_logits<<<eb, 256>>>(eidx, ridx, att + (size_t)l * HH * FF, l);
        k_exp<<<(ET * HH + 255) / 256, 256>>>(eidx);
        k_scatter<<<eb, 256>>>(eidx, osel[l]);
    }

    k_final<<<(out_size + 255) / 256, 256>>>(relations, out, out_size);
}

// round 3
// speedup vs baseline: 1.6261x; 1.0758x over previous
#include <cuda_runtime.h>
#include <math.h>

#define NN 20000
#define EE 100000
#define RR 1000
#define FF 128
#define HH 4
#define LL 4
#define HC 512          // HH*FF
#define ET (EE + NN)    // edges + self loops

// ---------------- scratch (static device globals; no allocation) -------------
__device__ __align__(256) float    g_h0[NN * FF];
__device__ __align__(256) float    g_h1[NN * FF];
__device__ __align__(256) float    g_xl[(size_t)NN * HC];
__device__ __align__(256) float    g_xr[(size_t)NN * HC];
__device__ __align__(256) float    g_relemb[(size_t)LL * RR * HC];
__device__ __align__(256) float    g_eemean[LL * HC];
__device__ __align__(256) float    g_eamean[FF];
__device__ __align__(256) int      g_hist[RR];
// CSR by destination node
__device__ __align__(256) int      g_deg[NN];
__device__ __align__(256) int      g_rowptr[NN + 1];
__device__ __align__(256) int      g_cursor[NN];
__device__ __align__(256) int      g_csrc[ET];
__device__ __align__(256) int      g_crel[ET];

// ---------------- helpers ----------------------------------------------------
__device__ __forceinline__ float lrelu(float v) { return v > 0.f ? v : 0.2f * v; }

__device__ __forceinline__ const float* sel_in(const float* p, int s) {
    return s == 0 ? p : (s == 1 ? g_h0 : g_h1);
}
__device__ __forceinline__ float* sel_out(int s) {
    return s == 1 ? g_h0 : g_h1;
}

__device__ __forceinline__ unsigned to_tf32(float v) {
    unsigned r;
    asm("cvt.rna.tf32.f32 %0, %1;" : "=r"(r) : "f"(v));
    return r;
}

// ---------------- precompute kernels -----------------------------------------
__global__ void k_zero() {
    int i = blockIdx.x * blockDim.x + threadIdx.x;
    if (i < RR) g_hist[i] = 0;
    if (i < NN) g_deg[i] = 0;
}

// histogram of relations + in-degree (incl. self loop)
__global__ void k_hist(const int* __restrict__ relidx, const int* __restrict__ eidx) {
    int e = blockIdx.x * blockDim.x + threadIdx.x;
    if (e < EE) {
        atomicAdd(&g_hist[relidx[e]], 1);
        atomicAdd(&g_deg[eidx[EE + e]], 1);
    } else if (e < ET) {
        atomicAdd(&g_deg[e - EE], 1);   // self loop
    }
}

// ea_mean[f] = sum_r hist[r] * relations[r][f] / E
__global__ void k_eamean(const float* __restrict__ relations) {
    int f = threadIdx.x;  // 128 threads, 1 block
    float s = 0.f;
    for (int r = 0; r < RR; r++)
        s += (float)g_hist[r] * relations[r * FF + f];
    g_eamean[f] = s * (1.0f / EE);
}

// ee_mean[l][c] = sum_f ea_mean[f] * We[l][f][c]
__global__ void k_eemean(const float* __restrict__ We) {
    int idx = blockIdx.x * blockDim.x + threadIdx.x;
    if (idx >= LL * HC) return;
    int l = idx / HC, c = idx % HC;
    const float* W = We + (size_t)l * FF * HC;
    float s = 0.f;
    #pragma unroll 8
    for (int f = 0; f < FF; f++)
        s += g_eamean[f] * W[f * HC + c];
    g_eemean[idx] = s;
}

// exclusive prefix sum of g_deg -> g_rowptr, g_cursor. Single block, 1024 thr.
__global__ void __launch_bounds__(1024) k_scan() {
    __shared__ int ssum[1024];
    int t = threadIdx.x;
    const int per = (NN + 1023) / 1024;   // 20
    int base = t * per;
    int s = 0;
    #pragma unroll
    for (int i = 0; i < per; i++) {
        int n = base + i;
        if (n < NN) s += g_deg[n];
    }
    int mysum = s;
    ssum[t] = s;
    __syncthreads();
    #pragma unroll
    for (int d = 1; d < 1024; d <<= 1) {
        int v = (t >= d) ? ssum[t - d] : 0;
        __syncthreads();
        ssum[t] += v;
        __syncthreads();
    }
    int off = ssum[t] - mysum;   // exclusive
    #pragma unroll
    for (int i = 0; i < per; i++) {
        int n = base + i;
        if (n < NN) {
            g_rowptr[n] = off;
            g_cursor[n] = off;
            off += g_deg[n];
        }
    }
    if (t == 1023) g_rowptr[NN] = ET;
}

// scatter edge (src, rel) into CSR slots
__global__ void k_fill(const int* __restrict__ eidx, const int* __restrict__ ridx) {
    int e = blockIdx.x * blockDim.x + threadIdx.x;
    if (e >= ET) return;
    int src, dst, rel;
    if (e < EE) { src = eidx[e]; dst = eidx[EE + e]; rel = ridx[e]; }
    else        { src = dst = e - EE; rel = -1; }
    int pos = atomicAdd(&g_cursor[dst], 1);
    g_csrc[pos] = src;
    g_crel[pos] = rel;
}

// ---------------- tf32 tensor-core GEMM --------------------------------------
// C[M,512] = A[M,128] @ B[128,512] (+bias)
// CTA tile 128x128, BK=32 (4 chunks), 8 warps (2x4), warp tile 64x32.
// mode 0: z in {0,1}: B = z? B1:B0, bias = z? bias1:bias0, C = z? g_xr:g_xl
// mode 1: z = layer:  B = B0 + z*FF*HC, C = g_relemb + z*RR*HC, no bias
#define TBM 128
#define TBN 128
#define TBK 32

__device__ __forceinline__ void mma_tf32(float c[4], const unsigned a[4],
                                         const unsigned b[2]) {
    asm volatile(
        "mma.sync.aligned.m16n8k8.row.col.f32.tf32.tf32.f32 "
        "{%0,%1,%2,%3}, {%4,%5,%6,%7}, {%8,%9}, {%0,%1,%2,%3};"
        : "+f"(c[0]), "+f"(c[1]), "+f"(c[2]), "+f"(c[3])
        : "r"(a[0]), "r"(a[1]), "r"(a[2]), "r"(a[3]), "r"(b[0]), "r"(b[1]));
}

__global__ void __launch_bounds__(256, 2)
k_tgemm(const float* __restrict__ Ap, int asel,
        const float* __restrict__ B0, const float* __restrict__ B1,
        const float* __restrict__ bias0, const float* __restrict__ bias1,
        int mode, int M)
{
    // fragment-permuted staging buffers (conflict-free fragment loads)
    __shared__ __align__(16) unsigned Aperm[4 * 8 * 32 * 4];   // [ks][mt][lane][slot]
    __shared__ __align__(16) unsigned Bperm[4 * 16 * 32 * 2];  // [ks][nt][lane][slot]

    const float* A = sel_in(Ap, asel);
    const float* B;
    const float* bias = nullptr;
    float* C;
    int z = blockIdx.z;
    if (mode == 0) {
        B    = z ? B1 : B0;
        bias = z ? bias1 : bias0;
        C    = z ? g_xr : g_xl;
    } else {
        B = B0 + (size_t)z * FF * HC;
        C = g_relemb + (size_t)z * RR * HC;
    }

    int bm = blockIdx.y * TBM, bn = blockIdx.x * TBN;
    int tid = threadIdx.x, lane = tid & 31, wid = tid >> 5;
    int warp_m = wid & 1, warp_n = wid >> 1;   // 2 x 4 warp grid

    float c[4][4][4];
    #pragma unroll
    for (int i = 0; i < 4; i++)
        #pragma unroll
        for (int j = 0; j < 4; j++)
            #pragma unroll
            for (int k = 0; k < 4; k++) c[i][j][k] = 0.f;

    for (int k0 = 0; k0 < FF; k0 += TBK) {
        // ---- stage A chunk (128 rows x 32 k) into fragment-permuted layout
        #pragma unroll
        for (int i = 0; i < 16; i++) {
            int idx = i * 256 + tid;
            int row = idx >> 5, kk = idx & 31;
            float v = 0.f;
            int gr = bm + row;
            if (gr < M) v = A[(size_t)gr * FF + k0 + kk];
            unsigned tv = to_tf32(v);
            int ks = kk >> 3, q = kk & 7, mt = row >> 4, r16 = row & 15;
            int ln   = ((r16 & 7) << 2) | (q & 3);
            int slot = (r16 >> 3) + ((q >> 2) << 1);
            Aperm[(((ks << 3) | mt) << 7) + (ln << 2) + slot] = tv;
        }
        // ---- stage B chunk (32 k x 128 cols)
        #pragma unroll
        for (int i = 0; i < 16; i++) {
            int idx = i * 256 + tid;
            int kk = idx >> 7, col = idx & 127;
            float v = B[(size_t)(k0 + kk) * HC + bn + col];
            unsigned tv = to_tf32(v);
            int ks = kk >> 3, q = kk & 7, nt = col >> 3;
            int ln   = ((col & 7) << 2) | (q & 3);
            int slot = q >> 2;
            Bperm[(((ks << 4) | nt) << 6) + (ln << 1) + slot] = tv;
        }
        __syncthreads();

        #pragma unroll
        for (int ks = 0; ks < 4; ks++) {
            unsigned a[4][4], b[4][2];
            #pragma unroll
            for (int mt = 0; mt < 4; mt++) {
                int mt_g = warp_m * 4 + mt;
                uint4 v = *(const uint4*)&Aperm[(((ks << 3) | mt_g) << 7) + (lane << 2)];
                a[mt][0] = v.x; a[mt][1] = v.y; a[mt][2] = v.z; a[mt][3] = v.w;
            }
            #pragma unroll
            for (int nt = 0; nt < 4; nt++) {
                int nt_g = warp_n * 4 + nt;
                uint2 v = *(const uint2*)&Bperm[(((ks << 4) | nt_g) << 6) + (lane << 1)];
                b[nt][0] = v.x; b[nt][1] = v.y;
            }
            #pragma unroll
            for (int mt = 0; mt < 4; mt++)
                #pragma unroll
                for (int nt = 0; nt < 4; nt++)
                    mma_tf32(c[mt][nt], a[mt], b[nt]);
        }
        __syncthreads();
    }

    // ---- epilogue: bias + store (float2 per fragment half)
    #pragma unroll
    for (int mt = 0; mt < 4; mt++) {
        int row = bm + warp_m * 64 + mt * 16 + (lane >> 2);
        #pragma unroll
        for (int nt = 0; nt < 4; nt++) {
            int col = bn + warp_n * 32 + nt * 8 + ((lane & 3) << 1);
            float b0 = 0.f, b1 = 0.f;
            if (bias) { b0 = bias[col]; b1 = bias[col + 1]; }
            if (row < M) {
                float2 v = make_float2(c[mt][nt][0] + b0, c[mt][nt][1] + b1);
                *(float2*)&C[(size_t)row * HC + col] = v;
            }
            if (row + 8 < M) {
                float2 v = make_float2(c[mt][nt][2] + b0, c[mt][nt][3] + b1);
                *(float2*)&C[(size_t)(row + 8) * HC + col] = v;
            }
        }
    }
}

// ---------------- fused edge kernel ------------------------------------------
// One warp per destination node. Online softmax over incident edges; each
// xl[src] float4 is read once and used for both the logit and the aggregation.
// out[n][f] = bias[f] + (1/H) * sum_h (sum_e alpha_eh * xl[src_e][h][f])
__global__ void __launch_bounds__(256)
k_edge_fused(const float* __restrict__ att_l, const float* __restrict__ bias_l,
             int layer, int osel) {
    int n = blockIdx.x * 8 + (threadIdx.x >> 5);
    int lane = threadIdx.x & 31;
    if (n >= NN) return;
    int c = lane * 4;

    // per-warp constants: xr[dst] fragment, att fragment
    float4 xr[HH], aw[HH];
    const float* pxr = g_xr + (size_t)n * HC;
    #pragma unroll
    for (int h = 0; h < HH; h++) {
        xr[h] = *(const float4*)(pxr + h * FF + c);
        aw[h] = *(const float4*)(att_l + h * FF + c);
    }

    float  m[HH], den[HH];
    float4 acc[HH];
    #pragma unroll
    for (int h = 0; h < HH; h++) {
        m[h] = -1e30f; den[h] = 0.f;
        acc[h] = make_float4(0.f, 0.f, 0.f, 0.f);
    }

    int i0 = g_rowptr[n], i1 = g_rowptr[n + 1];
    const float* rel_base = g_relemb + (size_t)layer * RR * HC;
    const float* mean_ee  = g_eemean + layer * HC;

    for (int i = i0; i < i1; i++) {
        int src = g_csrc[i];
        int rel = g_crel[i];
        const float* ee  = (rel >= 0) ? rel_base + (size_t)rel * HC : mean_ee;
        const float* pxl = g_xl + (size_t)src * HC;

        float4 xlv[HH];
        float  s[HH];
        #pragma unroll
        for (int h = 0; h < HH; h++) {
            int o = h * FF + c;
            float4 a = *(const float4*)(pxl + o);
            float4 g = *(const float4*)(ee + o);
            xlv[h] = a;
            float t0 = lrelu(a.x + xr[h].x + g.x);
            float t1 = lrelu(a.y + xr[h].y + g.y);
            float t2 = lrelu(a.z + xr[h].z + g.z);
            float t3 = lrelu(a.w + xr[h].w + g.w);
            s[h] = aw[h].x * t0 + aw[h].y * t1 + aw[h].z * t2 + aw[h].w * t3;
        }
        // butterfly all-reduce of the 4 head logits
        #pragma unroll
        for (int off = 16; off > 0; off >>= 1) {
            s[0] += __shfl_xor_sync(0xFFFFFFFFu, s[0], off);
            s[1] += __shfl_xor_sync(0xFFFFFFFFu, s[1], off);
            s[2] += __shfl_xor_sync(0xFFFFFFFFu, s[2], off);
            s[3] += __shfl_xor_sync(0xFFFFFFFFu, s[3], off);
        }
        // online softmax update
        #pragma unroll
        for (int h = 0; h < HH; h++) {
            float mn = fmaxf(m[h], s[h]);
            float sc = __expf(m[h] - mn);
            float p  = __expf(s[h] - mn);
            m[h] = mn;
            den[h] = den[h] * sc + p;
            acc[h].x = acc[h].x * sc + p * xlv[h].x;
            acc[h].y = acc[h].y * sc + p * xlv[h].y;
            acc[h].z = acc[h].z * sc + p * xlv[h].z;
            acc[h].w = acc[h].w * sc + p * xlv[h].w;
        }
    }

    float4 bv = *(const float4*)(bias_l + c);
    float4 o;
    o.x = bv.x; o.y = bv.y; o.z = bv.z; o.w = bv.w;
    #pragma unroll
    for (int h = 0; h < HH; h++) {
        float r = 0.25f / den[h];
        o.x += r * acc[h].x;
        o.y += r * acc[h].y;
        o.z += r * acc[h].z;
        o.w += r * acc[h].w;
    }
    *(float4*)(sel_out(osel) + (size_t)n * FF + c) = o;
}

// ---------------- output -----------------------------------------------------
__global__ void k_final(const float* __restrict__ relations, float* __restrict__ out,
                        int out_size) {
    int idx = blockIdx.x * blockDim.x + threadIdx.x;
    if (idx >= out_size) return;
    if (idx < NN * FF) out[idx] = g_h1[idx];
    else {
        int r = idx - NN * FF;
        if (r < RR * FF) out[idx] = relations[r];
        else out[idx] = 0.f;
    }
}

// ---------------- launch -----------------------------------------------------
extern "C" void kernel_launch(void* const* d_in, const int* in_sizes, int n_in,
                              void* d_out, int out_size) {
    const float* x         = (const float*)d_in[0];
    const int*   eidx      = (const int*)  d_in[1];
    const float* relations = (const float*)d_in[2];
    const int*   ridx      = (const int*)  d_in[3];
    const float* Wl        = (const float*)d_in[4];
    const float* bl        = (const float*)d_in[5];
    const float* Wr        = (const float*)d_in[6];
    const float* br        = (const float*)d_in[7];
    const float* We        = (const float*)d_in[8];
    const float* att       = (const float*)d_in[9];
    const float* bias      = (const float*)d_in[10];
    float* out = (float*)d_out;

    // ---- precompute: hist/deg, CSR, mean edge-attr, relation embeddings ----
    k_zero<<<(NN + 255) / 256, 256>>>();
    k_hist<<<(ET + 255) / 256, 256>>>(ridx, eidx);
    k_eamean<<<1, FF>>>(relations);
    k_scan<<<1, 1024>>>();
    k_fill<<<(ET + 255) / 256, 256>>>(eidx, ridx);
    {
        dim3 grid(HC / TBN, (RR + TBM - 1) / TBM, LL);
        k_tgemm<<<grid, 256>>>(relations, 0, We, nullptr, nullptr, nullptr, 1, RR);
    }
    k_eemean<<<(LL * HC + 255) / 256, 256>>>(We);

    // ---- layers ----
    const int asel[LL] = {0, 1, 2, 1};
    const int osel[LL] = {1, 2, 1, 2};
    dim3 ggrid(HC / TBN, (NN + TBM - 1) / TBM, 2);   // z: 0 -> xl, 1 -> xr
    int nb = (NN + 7) / 8;                 // blocks for warp-per-node kernel

    for (int l = 0; l < LL; l++) {
        k_tgemm<<<ggrid, 256>>>(x, asel[l],
                                Wl + (size_t)l * FF * HC, Wr + (size_t)l * FF * HC,
                                bl + (size_t)l * HC, br + (size_t)l * HC,
                                0, NN);
        k_edge_fused<<<nb, 256>>>(att + (size_t)l * HH * FF,
                                  bias + (size_t)l * FF, l, osel[l]);
    }

    k_final<<<(out_size + 255) / 256, 256>>>(relations, out, out_size);
}